// round 11
// baseline (speedup 1.0000x reference)
#include <cuda_runtime.h>
#include <cuda_bf16.h>
#include <math.h>
#include <cstdint>

#define HDIM   64
#define NROT   32
#define SEQ    4096
#define NROWS  (8 * 4096 * 16)       // 524288 rows of 64 floats
#define NBLOCKS (NROWS / (8 * 32))   // 2048: 8 warps x 32 rows

// B = M^T (blend @ r_matrix, RoPE col permutation folded), bf16 hi/lo split,
// stored DIRECTLY in mma.m16n8k16 B-fragment order:
//   g_B?4[(kc*4 + np)*32 + lane] = uint4{bh0, bh1, bh2, bh3}
// where bh[i] = bf16x2 of phys k-pair p2 = 8kc + 2*(l&3) + (i&1)
// at n = 16np + 8*(i>>1) + (l>>2). (Algebraically identical to the
// ldmatrix-on-SW128 path used in R8-R10.)
__device__ uint4 g_BH4[512];
__device__ uint4 g_BL4[512];

// ---------------------------------------------------------------------------
// Setup: one block, 256 threads. Blend(I) -> M = Blend @ R (RoPE column
// permutation folded in) -> bf16 hi/lo split written in fragment order.
// ---------------------------------------------------------------------------
__global__ void setup_kernel(const float* __restrict__ thetas,
                             const float* __restrict__ theta_scale,
                             const float* __restrict__ r_matrix,
                             const int*   __restrict__ pairs) {
    __shared__ float E[HDIM * HDIM];     // blend(I), then M
    __shared__ float sR[HDIM * HDIM];
    int t = threadIdx.x;                 // 256 threads

    #pragma unroll
    for (int i = 0; i < 16; i++) sR[t + 256 * i] = r_matrix[t + 256 * i];

    if (t < HDIM) {
        int r = t;
        float row[HDIM];
        #pragma unroll
        for (int c = 0; c < HDIM; c++) row[c] = (r == c) ? 1.0f : 0.0f;
        float ts = theta_scale[0];
        for (int st = 0; st < NROT; st++) {
            int i = pairs[2 * st + 0];
            int j = pairs[2 * st + 1];
            float th = thetas[st] * ts;
            float c = cosf(th);
            float s = sinf(th);
            float xi = row[i];
            float xj = row[j];
            float gi = xi * c + xj * s;
            float gj = -xi * s + xj * c;
            row[i] = (2.0f * gi + xi - 2.0f * gi * c) * (1.0f / 3.0f);
            row[j] = (2.0f * gj + xj - 2.0f * gi * s) * (1.0f / 3.0f);
        }
        #pragma unroll
        for (int c = 0; c < HDIM; c++) E[r * HDIM + c] = row[c];
    }
    __syncthreads();

    // M = E @ R_perm ; thread t -> row r = t>>2, cols dl+4k
    int r  = t >> 2;
    int dl = t & 3;
    float accv[16];
    #pragma unroll
    for (int k = 0; k < 16; k++) {
        int d = dl + 4 * k;
        int col = (d < 32) ? (2 * d) : (2 * (d - 32) + 1);
        float acc = 0.0f;
        #pragma unroll
        for (int c = 0; c < HDIM; c++)
            acc = fmaf(E[r * HDIM + c], sR[c * HDIM + col], acc);
        accv[k] = acc;
    }
    __syncthreads();   // all matmul reads of E done
    #pragma unroll
    for (int k = 0; k < 16; k++)
        E[r * HDIM + (dl + 4 * k)] = accv[k];   // E now holds M [k][d]
    __syncthreads();

    // Fragment-order split: idx -> (grp = kc*4+np, lane)
    for (int idx = t; idx < 512; idx += 256) {
        int grp = idx >> 5, l = idx & 31;
        int kc = grp >> 2, np = grp & 3;
        uint32_t bh[4], bl[4];
        #pragma unroll
        for (int i = 0; i < 4; i++) {
            int n  = 16 * np + 8 * (i >> 1) + (l >> 2);
            int p2 = 8 * kc + 2 * (l & 3) + (i & 1);
            float m0 = E[(2 * p2)     * HDIM + n];
            float m1 = E[(2 * p2 + 1) * HDIM + n];
            __nv_bfloat16 h0 = __float2bfloat16_rn(m0);
            __nv_bfloat16 h1 = __float2bfloat16_rn(m1);
            float r0 = m0 - __bfloat162float(h0);
            float r1 = m1 - __bfloat162float(h1);
            __nv_bfloat16 l0 = __float2bfloat16_rn(r0);
            __nv_bfloat16 l1 = __float2bfloat16_rn(r1);
            bh[i] = (unsigned)__bfloat16_as_ushort(h0) |
                    ((unsigned)__bfloat16_as_ushort(h1) << 16);
            bl[i] = (unsigned)__bfloat16_as_ushort(l0) |
                    ((unsigned)__bfloat16_as_ushort(l1) << 16);
        }
        g_BH4[idx] = make_uint4(bh[0], bh[1], bh[2], bh[3]);
        g_BL4[idx] = make_uint4(bl[0], bl[1], bl[2], bl[3]);
    }
}

// ---------------------------------------------------------------------------
// helpers
// ---------------------------------------------------------------------------
__device__ __forceinline__ void mma16816(float* c, const uint32_t* a,
                                         uint32_t b0, uint32_t b1) {
    asm volatile(
        "mma.sync.aligned.m16n8k16.row.col.f32.bf16.bf16.f32 "
        "{%0,%1,%2,%3}, {%4,%5,%6,%7}, {%8,%9}, {%0,%1,%2,%3};"
        : "+f"(c[0]), "+f"(c[1]), "+f"(c[2]), "+f"(c[3])
        : "r"(a[0]), "r"(a[1]), "r"(a[2]), "r"(a[3]), "r"(b0), "r"(b1));
}
// split float2 into packed bf16x2 hi + packed bf16x2 residual
__device__ __forceinline__ void split2(float vx, float vy, uint32_t& h, uint32_t& lo) {
    asm("cvt.rn.bf16x2.f32 %0, %1, %2;" : "=r"(h) : "f"(vy), "f"(vx));
    float rx = vx - __uint_as_float(h << 16);
    float ry = vy - __uint_as_float(h & 0xFFFF0000u);
    asm("cvt.rn.bf16x2.f32 %0, %1, %2;" : "=r"(lo) : "f"(ry), "f"(rx));
}
// Cody-Waite reduction (k <= 652 exact) + MUFU sincos
__device__ __forceinline__ void rope_sincos(float a, float& s, float& c) {
    float k = rintf(a * 0.15915494309189535f);
    float rr = fmaf(-k, 6.28125f, a);
    rr = fmaf(-k, 1.9353071795e-3f, rr);
    rr = fmaf(-k, 8.908910206762e-10f, rr);
    __sincosf(rr, &s, &c);
}

// ---------------------------------------------------------------------------
// Main kernel: out = RoPE_diag( x @ M ) via bf16 mma.sync with hi/lo split.
// NO shared memory, NO barriers: B fragments come straight from global in
// frag order (one coalesced LDG.128 per (kc,np), L1-resident after first use),
// A fragments straight from global via the frag-order k permutation folded
// into B at setup. Warp = 32 rows = 2 m16 strips; n-dim in 2 time-halves so
// acc = 32 regs. Front-batched A loads give MLP=16 per warp.
// ---------------------------------------------------------------------------
__global__ __launch_bounds__(256, 2)
void rot_mma_kernel(const float* __restrict__ x, float* __restrict__ out,
                    const float* __restrict__ inv_freq) {
    int tid = threadIdx.x, w = tid >> 5, l = tid & 31;
    int g = l >> 2, c = l & 3;
    int cb = 2 * c;

    // ---- 1) front-batched A loads: 16 independent LDG.128 ----
    size_t rb0 = ((size_t)blockIdx.x * 8 + w) * 32;    // strip0; strip1 = +16
    const float4* b4 = (const float4*)(x + rb0 * HDIM) + g * 16 + c;
    float4 v[4][4];   // [row-group g+8*rg][kc]
    #pragma unroll
    for (int rg = 0; rg < 4; rg++)
        #pragma unroll
        for (int kc = 0; kc < 4; kc++)
            v[rg][kc] = __ldg(b4 + rg * 128 + kc * 4);

    // ---- 2) convert to persistent A fragments (64 regs) ----
    uint32_t ah[2][4][4], al[2][4][4];   // [strip][kc][frag]
    #pragma unroll
    for (int s = 0; s < 2; s++)
        #pragma unroll
        for (int kc = 0; kc < 4; kc++) {
            float4 r0 = v[2 * s][kc];      // row g
            float4 r1 = v[2 * s + 1][kc];  // row g+8
            split2(r0.x, r0.y, ah[s][kc][0], al[s][kc][0]);
            split2(r1.x, r1.y, ah[s][kc][1], al[s][kc][1]);
            split2(r0.z, r0.w, ah[s][kc][2], al[s][kc][2]);
            split2(r1.z, r1.w, ah[s][kc][3], al[s][kc][3]);
        }

    const uint4* BH = g_BH4 + l;
    const uint4* BL = g_BL4 + l;

    // ---- 3) two n-halves ----
    #pragma unroll
    for (int h = 0; h < 2; h++) {
        float acc[2][16];
        #pragma unroll
        for (int s = 0; s < 2; s++)
            #pragma unroll
            for (int p = 0; p < 16; p++) acc[s][p] = 0.0f;

        #pragma unroll
        for (int kc = 0; kc < 4; kc++)
            #pragma unroll
            for (int j = 0; j < 2; j++) {        // j=0: y tiles, j=1: z tiles
                int np = h + 2 * j;
                uint4 bh = __ldg(BH + (kc * 4 + np) * 32);
                uint4 bl = __ldg(BL + (kc * 4 + np) * 32);
                uint32_t bhr[4] = {bh.x, bh.y, bh.z, bh.w};
                uint32_t blr[4] = {bl.x, bl.y, bl.z, bl.w};
                #pragma unroll
                for (int s = 0; s < 2; s++) {
                    float* a0 = acc[s] + 8 * j;
                    float* a1 = acc[s] + 8 * j + 4;
                    mma16816(a0, ah[s][kc], bhr[0], bhr[1]);
                    mma16816(a1, ah[s][kc], bhr[2], bhr[3]);
                    mma16816(a0, al[s][kc], bhr[0], bhr[1]);
                    mma16816(a1, al[s][kc], bhr[2], bhr[3]);
                    mma16816(a0, ah[s][kc], blr[0], blr[1]);
                    mma16816(a1, ah[s][kc], blr[2], blr[3]);
                }
            }

        // epilogue for this half: y tile (2h+j2) pairs z tile (2h+4+j2);
        // d0 = 16h + 8*j2 + cb
        #pragma unroll
        for (int s = 0; s < 2; s++) {
            size_t rb = rb0 + 16 * s;
            float posf = (float)(int)((rb >> 4) & (SEQ - 1));
            float* o0 = out + (rb + g) * HDIM;
            float* o1 = out + (rb + g + 8) * HDIM;
            #pragma unroll
            for (int j2 = 0; j2 < 2; j2++) {
                int d0 = 16 * h + 8 * j2 + cb;
                float2 fr = __ldg((const float2*)(inv_freq + d0));
                float2 cc, ss;
                rope_sincos(posf * fr.x, ss.x, cc.x);
                rope_sincos(posf * fr.y, ss.y, cc.y);
                const float* y = acc[s] + 4 * j2;
                const float* z = acc[s] + 8 + 4 * j2;
                float2 lo0, hi0, lo1, hi1;
                lo0.x = y[0] * cc.x - z[0] * ss.x;
                lo0.y = y[1] * cc.y - z[1] * ss.y;
                hi0.x = y[0] * ss.x + z[0] * cc.x;
                hi0.y = y[1] * ss.y + z[1] * cc.y;
                lo1.x = y[2] * cc.x - z[2] * ss.x;
                lo1.y = y[3] * cc.y - z[3] * ss.y;
                hi1.x = y[2] * ss.x + z[2] * cc.x;
                hi1.y = y[3] * ss.y + z[3] * cc.y;
                *(float2*)(o0 + d0)      = lo0;
                *(float2*)(o0 + 32 + d0) = hi0;
                *(float2*)(o1 + d0)      = lo1;
                *(float2*)(o1 + 32 + d0) = hi1;
            }
        }
    }
}

// ---------------------------------------------------------------------------
extern "C" void kernel_launch(void* const* d_in, const int* in_sizes, int n_in,
                              void* d_out, int out_size) {
    const float* x           = (const float*)d_in[0];
    const float* thetas      = (const float*)d_in[1];
    const float* theta_scale = (const float*)d_in[2];
    const float* r_matrix    = (const float*)d_in[3];
    const float* inv_freq    = (const float*)d_in[4];
    const int*   pairs       = (const int*)d_in[5];
    float* out = (float*)d_out;

    setup_kernel<<<1, 256>>>(thetas, theta_scale, r_matrix, pairs);
    rot_mma_kernel<<<NBLOCKS, 256>>>(x, out, inv_freq);
}